// round 16
// baseline (speedup 1.0000x reference)
#include <cuda_runtime.h>
#include <cuda_fp16.h>
#include <math.h>
#include <stdint.h>

#define N_NODES 10000
#define MPAD    10112           // 79 * 128
#define N_EDGES 160000
#define N_TOT   (N_EDGES + N_NODES)
#define G       64
#define D_IN    1280
#define D_HID   512
#define D_OUT   256
#define SCAN_BLKS 40
// chunk split: rows/nodes [0,5120) and [5120,10112)
#define C0_ROWS 5120
#define C0_GY   40
#define C1_ROW0 5120
#define C1_GY   39
#define C0_NODES 5120
#define C1_NODES (N_NODES - C0_NODES)   // 4880

// ---------------- scratch ----------------
__device__ int   g_deg[N_NODES];
__device__ float g_dis[N_NODES];
__device__ int   g_rowptr[N_NODES + 1];
__device__ int   g_cursor[N_NODES];
__device__ int   g_part[SCAN_BLKS];
__device__ int   g_poff[SCAN_BLKS];
__device__ int   g_col[N_TOT];
__device__ float g_val[N_TOT];
__device__ __half g_h1[(size_t)MPAD * D_HID];
__device__ float  g_h2[(size_t)MPAD * D_OUT];
__device__ __half g_x[(size_t)MPAD * D_IN];
__device__ __half g_a[(size_t)MPAD * D_HID];
__device__ __half g_w1[D_IN * D_HID];
__device__ __half g_w2[D_HID * D_HID];
__device__ __half g_w3[D_HID * D_HID];
__device__ __half g_w4[D_HID * D_OUT];
__device__ float g_pool[G * D_OUT];
__device__ int   g_gcnt[G];
__device__ int   g_goff[G + 1];

// ---------------- graph preprocessing ----------------
__global__ void init_kernel() {
    int i = blockIdx.x * blockDim.x + threadIdx.x;
    if (i < N_NODES) g_deg[i] = 1;
    if (i < G) g_gcnt[i] = 0;
}

__global__ void hist_kernel(const int* __restrict__ dst,
                            const int* __restrict__ batch) {
    int e = blockIdx.x * blockDim.x + threadIdx.x;
    if (e < N_EDGES) atomicAdd(&g_deg[dst[e]], 1);
    if (e < N_NODES) atomicAdd(&g_gcnt[batch[e]], 1);
}

__global__ void scan_part_kernel() {
    __shared__ int sdata[256];
    int t = threadIdx.x;
    int i = blockIdx.x * 256 + t;
    int v = (i < N_NODES) ? g_deg[i] : 0;
    sdata[t] = v;
    __syncthreads();
#pragma unroll
    for (int off = 1; off < 256; off <<= 1) {
        int tmp = (t >= off) ? sdata[t - off] : 0;
        __syncthreads();
        sdata[t] += tmp;
        __syncthreads();
    }
    if (i < N_NODES) g_rowptr[i] = sdata[t] - v;
    if (t == 255) g_part[blockIdx.x] = sdata[255];
}

__global__ void scan_mid_kernel() {
    __shared__ int sa[64], sb[64];
    int t = threadIdx.x;
    int v0 = 0;
    if (t < 64) { v0 = (t < SCAN_BLKS) ? g_part[t] : 0; sa[t] = v0; }
    else        { v0 = g_gcnt[t - 64]; sb[t - 64] = v0; }
    __syncthreads();
#pragma unroll
    for (int off = 1; off < 64; off <<= 1) {
        int v = 0;
        if (t < 64) { if (t >= off) v = sa[t - off]; }
        else        { if ((t - 64) >= off) v = sb[t - 64 - off]; }
        __syncthreads();
        if (t < 64) sa[t] += v; else sb[t - 64] += v;
        __syncthreads();
    }
    if (t < SCAN_BLKS) g_poff[t] = sa[t] - v0;
    if (t >= 64) {
        g_goff[t - 64] = sb[t - 64] - v0;
        if (t == 127) g_goff[G] = sb[63];
    }
}

__global__ void scan_add_kernel() {
    int t = threadIdx.x;
    int i = blockIdx.x * 256 + t;
    if (i >= N_NODES) return;
    int excl = g_rowptr[i] + g_poff[blockIdx.x];
    g_rowptr[i] = excl;
    g_cursor[i] = excl;
    g_dis[i] = rsqrtf((float)g_deg[i]);
    if (i == 0) g_rowptr[N_NODES] = N_TOT;
}

__global__ void fill_csr_kernel(const int* __restrict__ src,
                                const int* __restrict__ dst) {
    int e = blockIdx.x * blockDim.x + threadIdx.x;
    if (e >= N_TOT) return;
    int s, d;
    if (e < N_EDGES) { s = src[e]; d = dst[e]; }
    else             { s = d = e - N_EDGES; }
    int pos = atomicAdd(&g_cursor[d], 1);
    g_col[pos] = s;
    g_val[pos] = g_dis[s] * g_dis[d];
}

// ---------------- conversions ----------------
__global__ void wconv_kernel(const float* __restrict__ W, int K, int N, int layer) {
    __half* Wt;
    switch (layer) {
        case 1: Wt = g_w1; break;
        case 2: Wt = g_w2; break;
        case 3: Wt = g_w3; break;
        default: Wt = g_w4; break;
    }
    int idx = blockIdx.x * blockDim.x + threadIdx.x;
    if (idx >= K * N) return;
    int k = idx / N, n = idx - k * N;
    Wt[(size_t)n * K + k] = __float2half(W[idx]);
}

__global__ void xconv_kernel(const float* __restrict__ x) {
    int idx = blockIdx.x * blockDim.x + threadIdx.x;
    if (idx >= N_NODES * D_IN) return;
    g_x[idx] = __float2half(x[idx]);
}

// ---------------- GEMM: 128x128x32, occ 2 (R11 config) + row offset ----------------
#define GBK      32
#define ASTRIDE  40
#define TILE_W   2560
#define STAGE_W  5120
#define SMEM_BYTES (2 * STAGE_W * 4)

__device__ __forceinline__ void cp16(uint32_t dst, const void* src) {
    asm volatile("cp.async.ca.shared.global [%0], [%1], 16;" :: "r"(dst), "l"(src));
}

__device__ __forceinline__ void mma_f16(float c[4], const uint32_t a[4],
                                        uint32_t b0, uint32_t b1) {
    asm volatile(
        "mma.sync.aligned.m16n8k16.row.col.f32.f16.f16.f32 "
        "{%0,%1,%2,%3}, {%4,%5,%6,%7}, {%8,%9}, {%0,%1,%2,%3};"
        : "+f"(c[0]), "+f"(c[1]), "+f"(c[2]), "+f"(c[3])
        : "r"(a[0]), "r"(a[1]), "r"(a[2]), "r"(a[3]), "r"(b0), "r"(b1));
}

__global__ __launch_bounds__(256, 2) void mma_gemm_kernel(int asel, int layer,
                                                          int K, int N, int row0) {
    extern __shared__ __half smem[];
    const __half *A, *B;
    A = (asel == 0) ? g_x : g_a;
    switch (layer) {
        case 1: B = g_w1; break;
        case 2: B = g_w2; break;
        case 3: B = g_w3; break;
        default: B = g_w4; break;
    }
    int tid = threadIdx.x;
    int brow = row0 + blockIdx.y * 128;
    int bcol = blockIdx.x * 128;

    int lrow = tid >> 1;
    int lhalf = tid & 1;
    const __half* ag = A + (size_t)(brow + lrow) * K + lhalf * 16;
    const __half* bg = B + (size_t)(bcol + lrow) * K + lhalf * 16;
    uint32_t sbase = (uint32_t)__cvta_generic_to_shared(smem);
    uint32_t sdst = sbase + (uint32_t)(lrow * ASTRIDE + lhalf * 16) * 2;

    int warp = tid >> 5, lane = tid & 31;
    int wm = warp >> 2, wn = warp & 3;
    int group = lane >> 2, quad = lane & 3;

    float acc[4][4][4];
#pragma unroll
    for (int i = 0; i < 4; i++)
#pragma unroll
        for (int j = 0; j < 4; j++)
#pragma unroll
            for (int v = 0; v < 4; v++) acc[i][j][v] = 0.f;

    int NK = K / GBK;
    {
        cp16(sdst, ag);
        cp16(sdst + 16, (const char*)ag + 16);
        cp16(sdst + TILE_W * 4, bg);
        cp16(sdst + TILE_W * 4 + 16, (const char*)bg + 16);
        asm volatile("cp.async.commit_group;");
    }

    for (int it = 0; it < NK; it++) {
        if (it + 1 < NK) {
            int k0 = (it + 1) * GBK;
            uint32_t stg = ((it + 1) & 1) * (STAGE_W * 4);
            cp16(sdst + stg, ag + k0);
            cp16(sdst + stg + 16, (const char*)(ag + k0) + 16);
            cp16(sdst + stg + TILE_W * 4, bg + k0);
            cp16(sdst + stg + TILE_W * 4 + 16, (const char*)(bg + k0) + 16);
        }
        asm volatile("cp.async.commit_group;");
        asm volatile("cp.async.wait_group 1;");
        __syncthreads();

        const uint32_t* sw = (const uint32_t*)smem + (it & 1) * STAGE_W;
        const uint32_t* sA32 = sw;
        const uint32_t* sB32 = sw + TILE_W;

#pragma unroll
        for (int kk = 0; kk < 2; kk++) {
            int kb = kk * 8;
            uint32_t ah[4][4];
#pragma unroll
            for (int im = 0; im < 4; im++) {
                int r = wm * 64 + im * 16 + group;
                int i0 = r * 20 + kb + quad;
                int i1 = (r + 8) * 20 + kb + quad;
                ah[im][0] = sA32[i0];     ah[im][1] = sA32[i1];
                ah[im][2] = sA32[i0 + 4]; ah[im][3] = sA32[i1 + 4];
            }
#pragma unroll
            for (int in_ = 0; in_ < 4; in_++) {
                int n = wn * 32 + in_ * 8 + group;
                int j0 = n * 20 + kb + quad;
                uint32_t b0 = sB32[j0], b1 = sB32[j0 + 4];
#pragma unroll
                for (int im = 0; im < 4; im++) {
                    mma_f16(acc[im][in_], ah[im], b0, b1);
                }
            }
        }
        __syncthreads();
    }

#pragma unroll
    for (int im = 0; im < 4; im++) {
        int r = brow + wm * 64 + im * 16 + group;
#pragma unroll
        for (int in_ = 0; in_ < 4; in_++) {
            int c = bcol + wn * 32 + in_ * 8 + quad * 2;
            __half2 lo = __floats2half2_rn(acc[im][in_][0], acc[im][in_][1]);
            __half2 hi = __floats2half2_rn(acc[im][in_][2], acc[im][in_][3]);
            *(__half2*)(g_h1 + (size_t)r * N + c) = lo;
            *(__half2*)(g_h1 + (size_t)(r + 8) * N + c) = hi;
        }
    }
}

// ---------------- aggregation (layers 1-3), node-range, 2-edge pipeline ----------
// row = D_HID halves = 1024 B = 64 uint4. CORRECT stride: c * 64.
__global__ void aggregate_h_kernel(const float* __restrict__ bias, int n0, int cnt) {
    int i = n0 + blockIdx.x * 2 + (threadIdx.x >> 6);
    int t = threadIdx.x & 63;
    if (i >= n0 + cnt || i >= N_NODES) return;
    int s = g_rowptr[i], e = g_rowptr[i + 1];
    float acc[8];
#pragma unroll
    for (int q = 0; q < 8; q++) acc[q] = 0.f;
    const uint4* h4 = (const uint4*)g_h1;
    int p = s;
    for (; p + 2 <= e; p += 2) {
        int c0 = g_col[p], c1 = g_col[p + 1];
        float v0 = g_val[p], v1 = g_val[p + 1];
        uint4 r0 = h4[(size_t)c0 * 64 + t];
        uint4 r1 = h4[(size_t)c1 * 64 + t];
        const __half2* h0 = (const __half2*)&r0;
        const __half2* h1p = (const __half2*)&r1;
#pragma unroll
        for (int q = 0; q < 4; q++) {
            float2 f0 = __half22float2(h0[q]);
            float2 f1 = __half22float2(h1p[q]);
            acc[q * 2 + 0] += v0 * f0.x + v1 * f1.x;
            acc[q * 2 + 1] += v0 * f0.y + v1 * f1.y;
        }
    }
    if (p < e) {
        int c0 = g_col[p];
        float v0 = g_val[p];
        uint4 r0 = h4[(size_t)c0 * 64 + t];
        const __half2* h0 = (const __half2*)&r0;
#pragma unroll
        for (int q = 0; q < 4; q++) {
            float2 f0 = __half22float2(h0[q]);
            acc[q * 2 + 0] += v0 * f0.x;
            acc[q * 2 + 1] += v0 * f0.y;
        }
    }
    float4 b0 = ((const float4*)bias)[t * 2];
    float4 b1 = ((const float4*)bias)[t * 2 + 1];
    acc[0] += b0.x; acc[1] += b0.y; acc[2] += b0.z; acc[3] += b0.w;
    acc[4] += b1.x; acc[5] += b1.y; acc[6] += b1.z; acc[7] += b1.w;
    uint4 outp;
    __half2* op = (__half2*)&outp;
#pragma unroll
    for (int q = 0; q < 4; q++) {
        op[q] = __floats2half2_rn(fmaxf(acc[q * 2 + 0], 0.f),
                                  fmaxf(acc[q * 2 + 1], 0.f));
    }
    ((uint4*)(g_a + (size_t)i * D_HID))[t] = outp;
}

// ---------------- aggregation (layer 4), node-range, 2-edge pipeline ------------
// row = D_OUT halves = 512 B = 64 uint2. CORRECT stride: c * 64.
__global__ void aggregate_f32_kernel(const float* __restrict__ bias, int n0, int cnt) {
    int i = n0 + blockIdx.x * 2 + (threadIdx.x >> 6);
    int t = threadIdx.x & 63;
    if (i >= n0 + cnt || i >= N_NODES) return;
    int s = g_rowptr[i], e = g_rowptr[i + 1];
    float4 acc = make_float4(0.f, 0.f, 0.f, 0.f);
    const uint2* h2p = (const uint2*)g_h1;
    int p = s;
    for (; p + 2 <= e; p += 2) {
        int c0 = g_col[p], c1 = g_col[p + 1];
        float v0 = g_val[p], v1 = g_val[p + 1];
        uint2 r0 = h2p[(size_t)c0 * 64 + t];
        uint2 r1 = h2p[(size_t)c1 * 64 + t];
        const __half2* a0 = (const __half2*)&r0;
        const __half2* a1 = (const __half2*)&r1;
        float2 f00 = __half22float2(a0[0]), f01 = __half22float2(a0[1]);
        float2 f10 = __half22float2(a1[0]), f11 = __half22float2(a1[1]);
        acc.x += v0 * f00.x + v1 * f10.x;
        acc.y += v0 * f00.y + v1 * f10.y;
        acc.z += v0 * f01.x + v1 * f11.x;
        acc.w += v0 * f01.y + v1 * f11.y;
    }
    if (p < e) {
        int c0 = g_col[p];
        float v0 = g_val[p];
        uint2 r0 = h2p[(size_t)c0 * 64 + t];
        const __half2* a0 = (const __half2*)&r0;
        float2 f00 = __half22float2(a0[0]), f01 = __half22float2(a0[1]);
        acc.x += v0 * f00.x; acc.y += v0 * f00.y;
        acc.z += v0 * f01.x; acc.w += v0 * f01.y;
    }
    float4 b = ((const float4*)bias)[t];
    acc.x += b.x; acc.y += b.y; acc.z += b.z; acc.w += b.w;
    ((float4*)(g_h2 + (size_t)i * D_OUT))[t] = acc;
}

// ---------------- pooling + L2 normalize ----------------
__global__ void pool_kernel() {
    __shared__ float red[256];
    int g = blockIdx.x, t = threadIdx.x;
    int s = g_goff[g], e = g_goff[g + 1];
    float acc = 0.f;
    for (int n = s; n < e; n++) acc += g_h2[(size_t)n * D_OUT + t];
    float cnt = (float)(e - s);
    float mean = acc / fmaxf(cnt, 1.f);
    red[t] = mean * mean;
    __syncthreads();
    for (int off = 128; off > 0; off >>= 1) {
        if (t < off) red[t] += red[t + off];
        __syncthreads();
    }
    float nrm = sqrtf(red[0]);
    g_pool[g * D_OUT + t] = mean / fmaxf(nrm, 1e-12f);
}

// ---------------- classifier MLP head ----------------
__global__ void mlp_kernel(const float* __restrict__ vec,
                           const float* __restrict__ cW1, const float* __restrict__ cb1,
                           const float* __restrict__ cW2, const float* __restrict__ cb2,
                           const float* __restrict__ cW3, const float* __restrict__ cb3,
                           float* __restrict__ out) {
    __shared__ float comb[512];
    __shared__ float z1[256];
    __shared__ float z2[64];
    int g = blockIdx.x, t = threadIdx.x;
    comb[t] = g_pool[g * 256 + t];
    comb[256 + t] = vec[g * 256 + t];
    __syncthreads();
    float s1 = cb1[t];
    for (int k = 0; k < 512; k++) s1 += comb[k] * cW1[k * 256 + t];
    z1[t] = fmaxf(s1, 0.f);
    __syncthreads();
    if (t < 64) {
        float s2 = cb2[t];
        for (int k = 0; k < 256; k++) s2 += z1[k] * cW2[k * 64 + t];
        z2[t] = fmaxf(s2, 0.f);
    }
    __syncthreads();
    if (t == 0) {
        float s3 = cb3[0];
        for (int k = 0; k < 64; k++) s3 += z2[k] * cW3[k];
        out[g] = 1.f / (1.f + expf(-s3));
    }
}

// ---------------- launch ----------------
extern "C" void kernel_launch(void* const* d_in, const int* in_sizes, int n_in,
                              void* d_out, int out_size) {
    const float* x    = (const float*)d_in[0];
    const int*   ei   = (const int*)d_in[1];
    const int*   bat  = (const int*)d_in[2];
    const float* vec  = (const float*)d_in[3];
    const float* W1 = (const float*)d_in[4],  *b1 = (const float*)d_in[5];
    const float* W2 = (const float*)d_in[6],  *b2 = (const float*)d_in[7];
    const float* W3 = (const float*)d_in[8],  *b3 = (const float*)d_in[9];
    const float* W4 = (const float*)d_in[10], *b4 = (const float*)d_in[11];
    const float* cW1 = (const float*)d_in[12], *cb1 = (const float*)d_in[13];
    const float* cW2 = (const float*)d_in[14], *cb2 = (const float*)d_in[15];
    const float* cW3 = (const float*)d_in[16], *cb3 = (const float*)d_in[17];
    float* out = (float*)d_out;

    const int* src = ei;
    const int* dst = ei + N_EDGES;

    cudaFuncSetAttribute(mma_gemm_kernel,
                         cudaFuncAttributeMaxDynamicSharedMemorySize, SMEM_BYTES);

    // streams + events (created once; no device allocation)
    static cudaStream_t s_side = nullptr, s2 = nullptr;
    static cudaEvent_t ev[14];
    if (s_side == nullptr) {
        cudaStreamCreateWithFlags(&s_side, cudaStreamNonBlocking);
        cudaStreamCreateWithFlags(&s2, cudaStreamNonBlocking);
        for (int i = 0; i < 14; i++)
            cudaEventCreateWithFlags(&ev[i], cudaEventDisableTiming);
    }
    cudaEvent_t ev_fork = ev[0], ev_w1 = ev[1], ev_csr = ev[2], ev_xc = ev[3];
    cudaEvent_t e_m1 = ev[4], e_s1 = ev[5], e_m2 = ev[6], e_s2e = ev[7];
    cudaEvent_t e_m3 = ev[8], e_s3e = ev[9], e_m4 = ev[10], e_s4e = ev[11];
    cudaEvent_t e_sf = ev[12];

    dim3 blk(256);

    // fork
    cudaEventRecord(ev_fork, 0);
    cudaStreamWaitEvent(s_side, ev_fork, 0);
    cudaStreamWaitEvent(s2, ev_fork, 0);

    // side stream: wconv1 first (unblocks GEMM1), then CSR + wconv2-4
    wconv_kernel<<<(D_IN * D_HID + 255) / 256, 256, 0, s_side>>>(W1, D_IN, D_HID, 1);
    cudaEventRecord(ev_w1, s_side);
    init_kernel<<<(N_NODES + 255) / 256, 256, 0, s_side>>>();
    hist_kernel<<<(N_EDGES + 255) / 256, 256, 0, s_side>>>(dst, bat);
    scan_part_kernel<<<SCAN_BLKS, 256, 0, s_side>>>();
    scan_mid_kernel<<<1, 128, 0, s_side>>>();
    scan_add_kernel<<<SCAN_BLKS, 256, 0, s_side>>>();
    fill_csr_kernel<<<(N_TOT + 255) / 256, 256, 0, s_side>>>(src, dst);
    wconv_kernel<<<(D_HID * D_HID + 255) / 256, 256, 0, s_side>>>(W2, D_HID, D_HID, 2);
    wconv_kernel<<<(D_HID * D_HID + 255) / 256, 256, 0, s_side>>>(W3, D_HID, D_HID, 3);
    wconv_kernel<<<(D_HID * D_OUT + 255) / 256, 256, 0, s_side>>>(W4, D_HID, D_OUT, 4);
    cudaEventRecord(ev_csr, s_side);

    // main: xconv, then GEMM1 chunk0
    xconv_kernel<<<(N_NODES * D_IN + 255) / 256, 256>>>(x);
    cudaEventRecord(ev_xc, 0);
    cudaStreamWaitEvent(0, ev_w1, 0);
    mma_gemm_kernel<<<dim3(D_HID / 128, C0_GY), blk, SMEM_BYTES>>>(0, 1, D_IN, D_HID, 0);
    cudaEventRecord(e_m1, 0);

    // s2: GEMM1 chunk1
    cudaStreamWaitEvent(s2, ev_xc, 0);
    cudaStreamWaitEvent(s2, ev_w1, 0);
    mma_gemm_kernel<<<dim3(D_HID / 128, C1_GY), blk, SMEM_BYTES, s2>>>(0, 1, D_IN, D_HID, C1_ROW0);
    cudaEventRecord(e_s1, s2);

    // layer 1 agg + layer 2 GEMM
    cudaStreamWaitEvent(0, ev_csr, 0);
    cudaStreamWaitEvent(0, e_s1, 0);
    aggregate_h_kernel<<<C0_NODES / 2, 128>>>(b1, 0, C0_NODES);
    mma_gemm_kernel<<<dim3(D_HID / 128, C0_GY), blk, SMEM_BYTES>>>(1, 2, D_HID, D_HID, 0);
    cudaEventRecord(e_m2, 0);

    cudaStreamWaitEvent(s2, ev_csr, 0);
    cudaStreamWaitEvent(s2, e_m1, 0);
    aggregate_h_kernel<<<C1_NODES / 2, 128, 0, s2>>>(b1, C0_NODES, C1_NODES);
    mma_gemm_kernel<<<dim3(D_HID / 128, C1_GY), blk, SMEM_BYTES, s2>>>(1, 2, D_HID, D_HID, C1_ROW0);
    cudaEventRecord(e_s2e, s2);

    // layer 2 agg + layer 3 GEMM
    cudaStreamWaitEvent(0, e_s2e, 0);
    aggregate_h_kernel<<<C0_NODES / 2, 128>>>(b2, 0, C0_NODES);
    mma_gemm_kernel<<<dim3(D_HID / 128, C0_GY), blk, SMEM_BYTES>>>(1, 3, D_HID, D_HID, 0);
    cudaEventRecord(e_m3, 0);

    cudaStreamWaitEvent(s2, e_m2, 0);
    aggregate_h_kernel<<<C1_NODES / 2, 128, 0, s2>>>(b2, C0_NODES, C1_NODES);
    mma_gemm_kernel<<<dim3(D_HID / 128, C1_GY), blk, SMEM_BYTES, s2>>>(1, 3, D_HID, D_HID, C1_ROW0);
    cudaEventRecord(e_s3e, s2);

    // layer 3 agg + layer 4 GEMM
    cudaStreamWaitEvent(0, e_s3e, 0);
    aggregate_h_kernel<<<C0_NODES / 2, 128>>>(b3, 0, C0_NODES);
    mma_gemm_kernel<<<dim3(D_OUT / 128, C0_GY), blk, SMEM_BYTES>>>(1, 4, D_HID, D_OUT, 0);
    cudaEventRecord(e_m4, 0);

    cudaStreamWaitEvent(s2, e_m3, 0);
    aggregate_h_kernel<<<C1_NODES / 2, 128, 0, s2>>>(b3, C0_NODES, C1_NODES);
    mma_gemm_kernel<<<dim3(D_OUT / 128, C1_GY), blk, SMEM_BYTES, s2>>>(1, 4, D_HID, D_OUT, C1_ROW0);
    cudaEventRecord(e_s4e, s2);

    // layer 4 agg
    cudaStreamWaitEvent(0, e_s4e, 0);
    aggregate_f32_kernel<<<C0_NODES / 2, 128>>>(b4, 0, C0_NODES);

    cudaStreamWaitEvent(s2, e_m4, 0);
    aggregate_f32_kernel<<<C1_NODES / 2, 128, 0, s2>>>(b4, C0_NODES, C1_NODES);
    cudaEventRecord(e_sf, s2);

    // pooling + normalize + head
    cudaStreamWaitEvent(0, e_sf, 0);
    pool_kernel<<<G, 256>>>();
    mlp_kernel<<<G, 256>>>(vec, cW1, cb1, cW2, cb2, cW3, cb3, out);
}

// round 17
// speedup vs baseline: 1.1020x; 1.1020x over previous
#include <cuda_runtime.h>
#include <cuda_fp16.h>
#include <math.h>
#include <stdint.h>

#define N_NODES 10000
#define MPAD    10112           // 79 * 128
#define N_EDGES 160000
#define N_TOT   (N_EDGES + N_NODES)
#define G       64
#define D_IN    1280
#define D_HID   512
#define D_OUT   256
#define SCAN_BLKS 40
// chunk split: rows/nodes [0,5120) and [5120,10112)
#define C0_GY   40
#define C1_ROW0 5120
#define C1_GY   39
#define C0_NODES 5120
#define C1_NODES (N_NODES - C0_NODES)   // 4880

// ---------------- scratch ----------------
__device__ int   g_deg[N_NODES];
__device__ float g_dis[N_NODES];
__device__ int   g_rowptr[N_NODES + 1];
__device__ int   g_cursor[N_NODES];
__device__ int   g_part[SCAN_BLKS];
__device__ int   g_poff[SCAN_BLKS];
__device__ int   g_col[N_TOT];
__device__ float g_val[N_TOT];
__device__ __half g_h1[(size_t)MPAD * D_HID];
__device__ float  g_h2[(size_t)MPAD * D_OUT];
__device__ __half g_x[(size_t)MPAD * D_IN];
__device__ __half g_a[(size_t)MPAD * D_HID];
__device__ __half g_w1[D_IN * D_HID];
__device__ __half g_w2[D_HID * D_HID];
__device__ __half g_w3[D_HID * D_HID];
__device__ __half g_w4[D_HID * D_OUT];
__device__ float g_pool[G * D_OUT];
__device__ int   g_gcnt[G];
__device__ int   g_goff[G + 1];

// ---------------- graph preprocessing ----------------
__global__ void init_kernel() {
    int i = blockIdx.x * blockDim.x + threadIdx.x;
    if (i < N_NODES) g_deg[i] = 1;
    if (i < G) g_gcnt[i] = 0;
}

__global__ void hist_kernel(const int* __restrict__ dst,
                            const int* __restrict__ batch) {
    int e = blockIdx.x * blockDim.x + threadIdx.x;
    if (e < N_EDGES) atomicAdd(&g_deg[dst[e]], 1);
    if (e < N_NODES) atomicAdd(&g_gcnt[batch[e]], 1);
}

__global__ void scan_part_kernel() {
    __shared__ int sdata[256];
    int t = threadIdx.x;
    int i = blockIdx.x * 256 + t;
    int v = (i < N_NODES) ? g_deg[i] : 0;
    sdata[t] = v;
    __syncthreads();
#pragma unroll
    for (int off = 1; off < 256; off <<= 1) {
        int tmp = (t >= off) ? sdata[t - off] : 0;
        __syncthreads();
        sdata[t] += tmp;
        __syncthreads();
    }
    if (i < N_NODES) g_rowptr[i] = sdata[t] - v;
    if (t == 255) g_part[blockIdx.x] = sdata[255];
}

__global__ void scan_mid_kernel() {
    __shared__ int sa[64], sb[64];
    int t = threadIdx.x;
    int v0 = 0;
    if (t < 64) { v0 = (t < SCAN_BLKS) ? g_part[t] : 0; sa[t] = v0; }
    else        { v0 = g_gcnt[t - 64]; sb[t - 64] = v0; }
    __syncthreads();
#pragma unroll
    for (int off = 1; off < 64; off <<= 1) {
        int v = 0;
        if (t < 64) { if (t >= off) v = sa[t - off]; }
        else        { if ((t - 64) >= off) v = sb[t - 64 - off]; }
        __syncthreads();
        if (t < 64) sa[t] += v; else sb[t - 64] += v;
        __syncthreads();
    }
    if (t < SCAN_BLKS) g_poff[t] = sa[t] - v0;
    if (t >= 64) {
        g_goff[t - 64] = sb[t - 64] - v0;
        if (t == 127) g_goff[G] = sb[63];
    }
}

__global__ void scan_add_kernel() {
    int t = threadIdx.x;
    int i = blockIdx.x * 256 + t;
    if (i >= N_NODES) return;
    int excl = g_rowptr[i] + g_poff[blockIdx.x];
    g_rowptr[i] = excl;
    g_cursor[i] = excl;
    g_dis[i] = rsqrtf((float)g_deg[i]);
    if (i == 0) g_rowptr[N_NODES] = N_TOT;
}

__global__ void fill_csr_kernel(const int* __restrict__ src,
                                const int* __restrict__ dst) {
    int e = blockIdx.x * blockDim.x + threadIdx.x;
    if (e >= N_TOT) return;
    int s, d;
    if (e < N_EDGES) { s = src[e]; d = dst[e]; }
    else             { s = d = e - N_EDGES; }
    int pos = atomicAdd(&g_cursor[d], 1);
    g_col[pos] = s;
    g_val[pos] = g_dis[s] * g_dis[d];
}

// ---------------- conversions ----------------
// tiled transpose: W[K][N] fp32 -> Wt[N][K] fp16, coalesced both sides
__global__ void wconv_kernel(const float* __restrict__ W, int K, int N, int layer) {
    __half* Wt;
    switch (layer) {
        case 1: Wt = g_w1; break;
        case 2: Wt = g_w2; break;
        case 3: Wt = g_w3; break;
        default: Wt = g_w4; break;
    }
    __shared__ __half tile[32][33];
    int nb = blockIdx.x * 32, kb = blockIdx.y * 32;
    int tx = threadIdx.x & 31, ty = threadIdx.x >> 5;   // 32 x 8
#pragma unroll
    for (int j = 0; j < 32; j += 8) {
        tile[ty + j][tx] = __float2half(W[(size_t)(kb + ty + j) * N + nb + tx]);
    }
    __syncthreads();
#pragma unroll
    for (int j = 0; j < 32; j += 8) {
        Wt[(size_t)(nb + ty + j) * K + kb + tx] = tile[tx][ty + j];
    }
}

// vectorized x conversion: 4 elements per thread
__global__ void xconv_kernel(const float* __restrict__ x) {
    int idx = blockIdx.x * blockDim.x + threadIdx.x;
    if (idx >= N_NODES * D_IN / 4) return;
    float4 v = ((const float4*)x)[idx];
    __half2 lo = __floats2half2_rn(v.x, v.y);
    __half2 hi = __floats2half2_rn(v.z, v.w);
    uint2 o;
    o.x = *(uint32_t*)&lo;
    o.y = *(uint32_t*)&hi;
    ((uint2*)g_x)[idx] = o;
}

// ---------------- GEMM: 128x128x32, occ 2 (R11 config) + row offset ----------------
#define GBK      32
#define ASTRIDE  40
#define TILE_W   2560
#define STAGE_W  5120
#define SMEM_BYTES (2 * STAGE_W * 4)

__device__ __forceinline__ void cp16(uint32_t dst, const void* src) {
    asm volatile("cp.async.ca.shared.global [%0], [%1], 16;" :: "r"(dst), "l"(src));
}

__device__ __forceinline__ void mma_f16(float c[4], const uint32_t a[4],
                                        uint32_t b0, uint32_t b1) {
    asm volatile(
        "mma.sync.aligned.m16n8k16.row.col.f32.f16.f16.f32 "
        "{%0,%1,%2,%3}, {%4,%5,%6,%7}, {%8,%9}, {%0,%1,%2,%3};"
        : "+f"(c[0]), "+f"(c[1]), "+f"(c[2]), "+f"(c[3])
        : "r"(a[0]), "r"(a[1]), "r"(a[2]), "r"(a[3]), "r"(b0), "r"(b1));
}

__global__ __launch_bounds__(256, 2) void mma_gemm_kernel(int asel, int layer,
                                                          int K, int N, int row0) {
    extern __shared__ __half smem[];
    const __half *A, *B;
    A = (asel == 0) ? g_x : g_a;
    switch (layer) {
        case 1: B = g_w1; break;
        case 2: B = g_w2; break;
        case 3: B = g_w3; break;
        default: B = g_w4; break;
    }
    int tid = threadIdx.x;
    int brow = row0 + blockIdx.y * 128;
    int bcol = blockIdx.x * 128;

    int lrow = tid >> 1;
    int lhalf = tid & 1;
    const __half* ag = A + (size_t)(brow + lrow) * K + lhalf * 16;
    const __half* bg = B + (size_t)(bcol + lrow) * K + lhalf * 16;
    uint32_t sbase = (uint32_t)__cvta_generic_to_shared(smem);
    uint32_t sdst = sbase + (uint32_t)(lrow * ASTRIDE + lhalf * 16) * 2;

    int warp = tid >> 5, lane = tid & 31;
    int wm = warp >> 2, wn = warp & 3;
    int group = lane >> 2, quad = lane & 3;

    float acc[4][4][4];
#pragma unroll
    for (int i = 0; i < 4; i++)
#pragma unroll
        for (int j = 0; j < 4; j++)
#pragma unroll
            for (int v = 0; v < 4; v++) acc[i][j][v] = 0.f;

    int NK = K / GBK;
    {
        cp16(sdst, ag);
        cp16(sdst + 16, (const char*)ag + 16);
        cp16(sdst + TILE_W * 4, bg);
        cp16(sdst + TILE_W * 4 + 16, (const char*)bg + 16);
        asm volatile("cp.async.commit_group;");
    }

    for (int it = 0; it < NK; it++) {
        if (it + 1 < NK) {
            int k0 = (it + 1) * GBK;
            uint32_t stg = ((it + 1) & 1) * (STAGE_W * 4);
            cp16(sdst + stg, ag + k0);
            cp16(sdst + stg + 16, (const char*)(ag + k0) + 16);
            cp16(sdst + stg + TILE_W * 4, bg + k0);
            cp16(sdst + stg + TILE_W * 4 + 16, (const char*)(bg + k0) + 16);
        }
        asm volatile("cp.async.commit_group;");
        asm volatile("cp.async.wait_group 1;");
        __syncthreads();

        const uint32_t* sw = (const uint32_t*)smem + (it & 1) * STAGE_W;
        const uint32_t* sA32 = sw;
        const uint32_t* sB32 = sw + TILE_W;

#pragma unroll
        for (int kk = 0; kk < 2; kk++) {
            int kb = kk * 8;
            uint32_t ah[4][4];
#pragma unroll
            for (int im = 0; im < 4; im++) {
                int r = wm * 64 + im * 16 + group;
                int i0 = r * 20 + kb + quad;
                int i1 = (r + 8) * 20 + kb + quad;
                ah[im][0] = sA32[i0];     ah[im][1] = sA32[i1];
                ah[im][2] = sA32[i0 + 4]; ah[im][3] = sA32[i1 + 4];
            }
#pragma unroll
            for (int in_ = 0; in_ < 4; in_++) {
                int n = wn * 32 + in_ * 8 + group;
                int j0 = n * 20 + kb + quad;
                uint32_t b0 = sB32[j0], b1 = sB32[j0 + 4];
#pragma unroll
                for (int im = 0; im < 4; im++) {
                    mma_f16(acc[im][in_], ah[im], b0, b1);
                }
            }
        }
        __syncthreads();
    }

#pragma unroll
    for (int im = 0; im < 4; im++) {
        int r = brow + wm * 64 + im * 16 + group;
#pragma unroll
        for (int in_ = 0; in_ < 4; in_++) {
            int c = bcol + wn * 32 + in_ * 8 + quad * 2;
            __half2 lo = __floats2half2_rn(acc[im][in_][0], acc[im][in_][1]);
            __half2 hi = __floats2half2_rn(acc[im][in_][2], acc[im][in_][3]);
            *(__half2*)(g_h1 + (size_t)r * N + c) = lo;
            *(__half2*)(g_h1 + (size_t)(r + 8) * N + c) = hi;
        }
    }
}

// ---------------- aggregation (layers 1-3), node-range (R15 exact form) ----------
__global__ void aggregate_h_kernel(const float* __restrict__ bias, int n0, int cnt) {
    int i = n0 + blockIdx.x * 2 + (threadIdx.x >> 6);
    int t = threadIdx.x & 63;
    if (i >= n0 + cnt || i >= N_NODES) return;
    int s = g_rowptr[i], e = g_rowptr[i + 1];
    float acc[8];
#pragma unroll
    for (int q = 0; q < 8; q++) acc[q] = 0.f;
    for (int p = s; p < e; p++) {
        int c = g_col[p];
        float v = g_val[p];
        uint4 raw = ((const uint4*)(g_h1 + (size_t)c * D_HID))[t];
        const __half2* hp = (const __half2*)&raw;
#pragma unroll
        for (int q = 0; q < 4; q++) {
            float2 f = __half22float2(hp[q]);
            acc[q * 2 + 0] += v * f.x;
            acc[q * 2 + 1] += v * f.y;
        }
    }
    float4 b0 = ((const float4*)bias)[t * 2];
    float4 b1 = ((const float4*)bias)[t * 2 + 1];
    acc[0] += b0.x; acc[1] += b0.y; acc[2] += b0.z; acc[3] += b0.w;
    acc[4] += b1.x; acc[5] += b1.y; acc[6] += b1.z; acc[7] += b1.w;
    uint4 outp;
    __half2* op = (__half2*)&outp;
#pragma unroll
    for (int q = 0; q < 4; q++) {
        op[q] = __floats2half2_rn(fmaxf(acc[q * 2 + 0], 0.f),
                                  fmaxf(acc[q * 2 + 1], 0.f));
    }
    ((uint4*)(g_a + (size_t)i * D_HID))[t] = outp;
}

// ---------------- aggregation (layer 4), node-range (R15 exact form) ------------
__global__ void aggregate_f32_kernel(const float* __restrict__ bias, int n0, int cnt) {
    int i = n0 + blockIdx.x * 2 + (threadIdx.x >> 6);
    int t = threadIdx.x & 63;
    if (i >= n0 + cnt || i >= N_NODES) return;
    int s = g_rowptr[i], e = g_rowptr[i + 1];
    float4 acc = make_float4(0.f, 0.f, 0.f, 0.f);
    for (int p = s; p < e; p++) {
        int c = g_col[p];
        float v = g_val[p];
        uint2 raw = ((const uint2*)(g_h1 + (size_t)c * D_OUT))[t];
        const __half2* hp = (const __half2*)&raw;
        float2 f0 = __half22float2(hp[0]);
        float2 f1 = __half22float2(hp[1]);
        acc.x += v * f0.x; acc.y += v * f0.y; acc.z += v * f1.x; acc.w += v * f1.y;
    }
    float4 b = ((const float4*)bias)[t];
    acc.x += b.x; acc.y += b.y; acc.z += b.z; acc.w += b.w;
    ((float4*)(g_h2 + (size_t)i * D_OUT))[t] = acc;
}

// ---------------- pooling + L2 normalize ----------------
__global__ void pool_kernel() {
    __shared__ float red[256];
    int g = blockIdx.x, t = threadIdx.x;
    int s = g_goff[g], e = g_goff[g + 1];
    float acc = 0.f;
    for (int n = s; n < e; n++) acc += g_h2[(size_t)n * D_OUT + t];
    float cnt = (float)(e - s);
    float mean = acc / fmaxf(cnt, 1.f);
    red[t] = mean * mean;
    __syncthreads();
    for (int off = 128; off > 0; off >>= 1) {
        if (t < off) red[t] += red[t + off];
        __syncthreads();
    }
    float nrm = sqrtf(red[0]);
    g_pool[g * D_OUT + t] = mean / fmaxf(nrm, 1e-12f);
}

// ---------------- classifier MLP head ----------------
__global__ void mlp_kernel(const float* __restrict__ vec,
                           const float* __restrict__ cW1, const float* __restrict__ cb1,
                           const float* __restrict__ cW2, const float* __restrict__ cb2,
                           const float* __restrict__ cW3, const float* __restrict__ cb3,
                           float* __restrict__ out) {
    __shared__ float comb[512];
    __shared__ float z1[256];
    __shared__ float z2[64];
    int g = blockIdx.x, t = threadIdx.x;
    comb[t] = g_pool[g * 256 + t];
    comb[256 + t] = vec[g * 256 + t];
    __syncthreads();
    float s1 = cb1[t];
    for (int k = 0; k < 512; k++) s1 += comb[k] * cW1[k * 256 + t];
    z1[t] = fmaxf(s1, 0.f);
    __syncthreads();
    if (t < 64) {
        float s2 = cb2[t];
        for (int k = 0; k < 256; k++) s2 += z1[k] * cW2[k * 64 + t];
        z2[t] = fmaxf(s2, 0.f);
    }
    __syncthreads();
    if (t == 0) {
        float s3 = cb3[0];
        for (int k = 0; k < 64; k++) s3 += z2[k] * cW3[k];
        out[g] = 1.f / (1.f + expf(-s3));
    }
}

// ---------------- launch ----------------
extern "C" void kernel_launch(void* const* d_in, const int* in_sizes, int n_in,
                              void* d_out, int out_size) {
    const float* x    = (const float*)d_in[0];
    const int*   ei   = (const int*)d_in[1];
    const int*   bat  = (const int*)d_in[2];
    const float* vec  = (const float*)d_in[3];
    const float* W1 = (const float*)d_in[4],  *b1 = (const float*)d_in[5];
    const float* W2 = (const float*)d_in[6],  *b2 = (const float*)d_in[7];
    const float* W3 = (const float*)d_in[8],  *b3 = (const float*)d_in[9];
    const float* W4 = (const float*)d_in[10], *b4 = (const float*)d_in[11];
    const float* cW1 = (const float*)d_in[12], *cb1 = (const float*)d_in[13];
    const float* cW2 = (const float*)d_in[14], *cb2 = (const float*)d_in[15];
    const float* cW3 = (const float*)d_in[16], *cb3 = (const float*)d_in[17];
    float* out = (float*)d_out;

    const int* src = ei;
    const int* dst = ei + N_EDGES;

    cudaFuncSetAttribute(mma_gemm_kernel,
                         cudaFuncAttributeMaxDynamicSharedMemorySize, SMEM_BYTES);

    // streams + events (created once; no device allocation)
    static cudaStream_t s_side = nullptr, s2 = nullptr;
    static cudaEvent_t ev[14];
    if (s_side == nullptr) {
        cudaStreamCreateWithFlags(&s_side, cudaStreamNonBlocking);
        cudaStreamCreateWithFlags(&s2, cudaStreamNonBlocking);
        for (int i = 0; i < 14; i++)
            cudaEventCreateWithFlags(&ev[i], cudaEventDisableTiming);
    }
    cudaEvent_t ev_fork = ev[0], ev_w1 = ev[1], ev_csr = ev[2], ev_xc = ev[3];
    cudaEvent_t e_m1 = ev[4], e_s1 = ev[5], e_m2 = ev[6], e_s2e = ev[7];
    cudaEvent_t e_m3 = ev[8], e_s3e = ev[9], e_m4 = ev[10], e_s4e = ev[11];
    cudaEvent_t e_sf = ev[12];

    dim3 blk(256);

    // fork
    cudaEventRecord(ev_fork, 0);
    cudaStreamWaitEvent(s_side, ev_fork, 0);
    cudaStreamWaitEvent(s2, ev_fork, 0);

    // side stream: wconv1 first (unblocks GEMM1), then CSR + wconv2-4
    wconv_kernel<<<dim3(D_HID / 32, D_IN / 32), 256, 0, s_side>>>(W1, D_IN, D_HID, 1);
    cudaEventRecord(ev_w1, s_side);
    init_kernel<<<(N_NODES + 255) / 256, 256, 0, s_side>>>();
    hist_kernel<<<(N_EDGES + 255) / 256, 256, 0, s_side>>>(dst, bat);
    scan_part_kernel<<<SCAN_BLKS, 256, 0, s_side>>>();
    scan_mid_kernel<<<1, 128, 0, s_side>>>();
    scan_add_kernel<<<SCAN_BLKS, 256, 0, s_side>>>();
    fill_csr_kernel<<<(N_TOT + 255) / 256, 256, 0, s_side>>>(src, dst);
    wconv_kernel<<<dim3(D_HID / 32, D_HID / 32), 256, 0, s_side>>>(W2, D_HID, D_HID, 2);
    wconv_kernel<<<dim3(D_HID / 32, D_HID / 32), 256, 0, s_side>>>(W3, D_HID, D_HID, 3);
    wconv_kernel<<<dim3(D_OUT / 32, D_HID / 32), 256, 0, s_side>>>(W4, D_HID, D_OUT, 4);
    cudaEventRecord(ev_csr, s_side);

    // main: xconv (vectorized), then GEMM1 chunk0
    xconv_kernel<<<(N_NODES * D_IN / 4 + 255) / 256, 256>>>(x);
    cudaEventRecord(ev_xc, 0);
    cudaStreamWaitEvent(0, ev_w1, 0);
    mma_gemm_kernel<<<dim3(D_HID / 128, C0_GY), blk, SMEM_BYTES>>>(0, 1, D_IN, D_HID, 0);
    cudaEventRecord(e_m1, 0);

    // s2: GEMM1 chunk1
    cudaStreamWaitEvent(s2, ev_xc, 0);
    cudaStreamWaitEvent(s2, ev_w1, 0);
    mma_gemm_kernel<<<dim3(D_HID / 128, C1_GY), blk, SMEM_BYTES, s2>>>(0, 1, D_IN, D_HID, C1_ROW0);
    cudaEventRecord(e_s1, s2);

    // layer 1 agg + layer 2 GEMM
    cudaStreamWaitEvent(0, ev_csr, 0);
    cudaStreamWaitEvent(0, e_s1, 0);
    aggregate_h_kernel<<<C0_NODES / 2, 128>>>(b1, 0, C0_NODES);
    mma_gemm_kernel<<<dim3(D_HID / 128, C0_GY), blk, SMEM_BYTES>>>(1, 2, D_HID, D_HID, 0);
    cudaEventRecord(e_m2, 0);

    cudaStreamWaitEvent(s2, ev_csr, 0);
    cudaStreamWaitEvent(s2, e_m1, 0);
    aggregate_h_kernel<<<C1_NODES / 2, 128, 0, s2>>>(b1, C0_NODES, C1_NODES);
    mma_gemm_kernel<<<dim3(D_HID / 128, C1_GY), blk, SMEM_BYTES, s2>>>(1, 2, D_HID, D_HID, C1_ROW0);
    cudaEventRecord(e_s2e, s2);

    // layer 2 agg + layer 3 GEMM
    cudaStreamWaitEvent(0, e_s2e, 0);
    aggregate_h_kernel<<<C0_NODES / 2, 128>>>(b2, 0, C0_NODES);
    mma_gemm_kernel<<<dim3(D_HID / 128, C0_GY), blk, SMEM_BYTES>>>(1, 3, D_HID, D_HID, 0);
    cudaEventRecord(e_m3, 0);

    cudaStreamWaitEvent(s2, e_m2, 0);
    aggregate_h_kernel<<<C1_NODES / 2, 128, 0, s2>>>(b2, C0_NODES, C1_NODES);
    mma_gemm_kernel<<<dim3(D_HID / 128, C1_GY), blk, SMEM_BYTES, s2>>>(1, 3, D_HID, D_HID, C1_ROW0);
    cudaEventRecord(e_s3e, s2);

    // layer 3 agg + layer 4 GEMM
    cudaStreamWaitEvent(0, e_s3e, 0);
    aggregate_h_kernel<<<C0_NODES / 2, 128>>>(b3, 0, C0_NODES);
    mma_gemm_kernel<<<dim3(D_OUT / 128, C0_GY), blk, SMEM_BYTES>>>(1, 4, D_HID, D_OUT, 0);
    cudaEventRecord(e_m4, 0);

    cudaStreamWaitEvent(s2, e_m3, 0);
    aggregate_h_kernel<<<C1_NODES / 2, 128, 0, s2>>>(b3, C0_NODES, C1_NODES);
    mma_gemm_kernel<<<dim3(D_OUT / 128, C1_GY), blk, SMEM_BYTES, s2>>>(1, 4, D_HID, D_OUT, C1_ROW0);
    cudaEventRecord(e_s4e, s2);

    // layer 4 agg
    cudaStreamWaitEvent(0, e_s4e, 0);
    aggregate_f32_kernel<<<C0_NODES / 2, 128>>>(b4, 0, C0_NODES);

    cudaStreamWaitEvent(s2, e_m4, 0);
    aggregate_f32_kernel<<<C1_NODES / 2, 128, 0, s2>>>(b4, C0_NODES, C1_NODES);
    cudaEventRecord(e_sf, s2);

    // pooling + normalize + head
    cudaStreamWaitEvent(0, e_sf, 0);
    pool_kernel<<<G, 256>>>();
    mlp_kernel<<<G, 256>>>(vec, cW1, cb1, cW2, cb2, cW3, cb3, out);
}